// round 10
// baseline (speedup 1.0000x reference)
#include <cuda_runtime.h>
#include <cuda_bf16.h>
#include <cstdint>

// Embedding gather: out[b, t, :] = weight[idxes[b, t], :]
// idxes: [8, 2048] int32, weight: [50257, 1024] f32, out: [8,2048,1024] f32
//
// R10: grid-parallelism sweep, next point.
//   1 row /16384 CTAs (no stcs, MLP1): 23.0us  [R1]
//   4 rows/ 4096 CTAs:                 16.9us  [R9, best]
//   8 rows/ 2048 CTAs:                 18.5us  [R6]
//  16 rows/ 1024 CTAs:                 23.1us  [R7]
// This round: 2 rows/CTA -> 8192 CTAs. Finer-grained CTAs reduce the
// cross-CTA L1tex queue spread and wave-tail imbalance; MLP=2 per thread is
// the risk (R1's MLP=1 was latency-starved). __ldg reads (weight stays
// L2-resident across graph replays) + __stcs writes (evict-first).

#define FEATURES 1024
#define VEC4_PER_ROW (FEATURES / 4)   // 256
#define ROWS_PER_CTA 2

__global__ __launch_bounds__(256) void embedding_gather_stcs2_kernel(
    const int* __restrict__ idxes,
    const float4* __restrict__ weight,
    float4* __restrict__ out,
    int n_rows)
{
    const int t = threadIdx.x;                     // 0..255 = column slot
    const int base = blockIdx.x * ROWS_PER_CTA;

    if (base + ROWS_PER_CTA <= n_rows) {
        // One vectorized broadcast index load (int2).
        int2 iv = __ldg((const int2*)(idxes + base));
        int idx[ROWS_PER_CTA] = {iv.x, iv.y};

        float4 v[ROWS_PER_CTA];
#pragma unroll
        for (int r = 0; r < ROWS_PER_CTA; r++)
            v[r] = __ldg(weight + (size_t)idx[r] * VEC4_PER_ROW + t);

#pragma unroll
        for (int r = 0; r < ROWS_PER_CTA; r++)
            __stcs(out + (size_t)(base + r) * VEC4_PER_ROW + t, v[r]);
    } else {
        // Tail (unused at 16384 rows; kept for safety).
        for (int r = 0; r < ROWS_PER_CTA; r++) {
            int row = base + r;
            if (row >= n_rows) break;
            int src = idxes[row];
            __stcs(out + (size_t)row * VEC4_PER_ROW + t,
                   __ldg(weight + (size_t)src * VEC4_PER_ROW + t));
        }
    }
}

extern "C" void kernel_launch(void* const* d_in, const int* in_sizes, int n_in,
                              void* d_out, int out_size)
{
    const int*    idxes  = (const int*)d_in[0];
    const float4* weight = (const float4*)d_in[1];
    float4*       out    = (float4*)d_out;

    int n_rows = in_sizes[0];      // 8 * 2048 = 16384
    int n_ctas = (n_rows + ROWS_PER_CTA - 1) / ROWS_PER_CTA;

    embedding_gather_stcs2_kernel<<<n_ctas, 256>>>(idxes, weight, out, n_rows);
}